// round 5
// baseline (speedup 1.0000x reference)
#include <cuda_runtime.h>

#define BQ   4
#define NPT  16384
#define MQ   2048
#define CF   128
#define NS   32
#define PTOT (BQ*MQ)        // 8192 query points
#define COLS (PTOT*NS)      // 262144 GEMM columns
#define R2   9.0f
#define EPSV 1e-5f

// ---------------- static scratch (allocation-free rule) ----------------
__device__ float d_h0[64*PTOT];
__device__ float d_h1[3*PTOT];
__device__ float d_nxyz[PTOT*3];
__device__ float d_featT[BQ*NPT*CF];      // 32 MB: features transposed to [b][n][c]
__device__ int   d_idx[COLS];
__device__ float d_out0[128*COLS];        // 134 MB: pre-BN layer-0 activations
__device__ float d_pmax[256*PTOT];
__device__ float d_pmin[256*PTOT];
__device__ float d_stats[768];            // [0:128) m0sum [128:256) m0sq [256:512) m1sum [512:768) m1sq
__device__ float d_sc0[64], d_bi0[64], d_sc1[3], d_bi1[3];
__device__ float d_scm0[128], d_bim0[128], d_scm1[256], d_bim1[256];

// ---------------- packed f32x2 helpers ----------------
__device__ __forceinline__ unsigned long long pack2(float x){
    unsigned long long r; unsigned u = __float_as_uint(x);
    asm("mov.b64 %0, {%1, %1};" : "=l"(r) : "r"(u));
    return r;
}
__device__ __forceinline__ unsigned long long ffma2(unsigned long long a,
                                                    unsigned long long b,
                                                    unsigned long long c){
    unsigned long long d;
    asm("fma.rn.f32x2 %0, %1, %2, %3;" : "=l"(d) : "l"(a), "l"(b), "l"(c));
    return d;
}
__device__ __forceinline__ void unpack2(unsigned long long v, float& lo, float& hi){
    unsigned a, b;
    asm("mov.b64 {%0, %1}, %2;" : "=r"(a), "=r"(b) : "l"(v));
    lo = __uint_as_float(a); hi = __uint_as_float(b);
}

// ---------------- misc small kernels ----------------
__global__ void kzero(){
    int i = blockIdx.x*blockDim.x + threadIdx.x;
    if (i < 768) d_stats[i] = 0.f;
}

// shift layer 0 pre-BN: h0[c][p] = sum_d w0[c][d]*ffps[p][d]
__global__ void ks1(const float* __restrict__ ffps, const float* __restrict__ w0){
    int p = blockIdx.x*blockDim.x + threadIdx.x;
    float f0 = ffps[p*3+0], f1 = ffps[p*3+1], f2 = ffps[p*3+2];
    #pragma unroll 4
    for (int c = 0; c < 64; c++){
        float v = w0[c*3+0]*f0 + w0[c*3+1]*f1 + w0[c*3+2]*f2;
        d_h0[c*PTOT + p] = v;
    }
}

// generic per-channel stats over PTOT elements (shift layers)
__global__ void kstat(int which, const float* __restrict__ g, const float* __restrict__ bb){
    __shared__ float ss[256], sq[256];
    int c = blockIdx.x;
    const float* buf = (which == 0 ? d_h0 : d_h1) + c*PTOT;
    float s = 0.f, q = 0.f;
    for (int i = threadIdx.x; i < PTOT; i += 256){
        float v = buf[i]; s += v; q = fmaf(v, v, q);
    }
    ss[threadIdx.x] = s; sq[threadIdx.x] = q; __syncthreads();
    for (int o = 128; o > 0; o >>= 1){
        if (threadIdx.x < o){
            ss[threadIdx.x] += ss[threadIdx.x+o];
            sq[threadIdx.x] += sq[threadIdx.x+o];
        }
        __syncthreads();
    }
    if (threadIdx.x == 0){
        float mean = ss[0] / (float)PTOT;
        float var  = sq[0] / (float)PTOT - mean*mean;
        float scl  = g[c] * rsqrtf(var + EPSV);
        if (which == 0){ d_sc0[c] = scl; d_bi0[c] = fmaf(-mean, scl, bb[c]); }
        else           { d_sc1[c] = scl; d_bi1[c] = fmaf(-mean, scl, bb[c]); }
    }
}

// shift layer 1 pre-BN: h1[o][p] = sum_c w1[o][c]*relu(bn(h0[c][p]))
__global__ void ks2(const float* __restrict__ w1){
    int p = blockIdx.x*blockDim.x + threadIdx.x;
    float a0 = 0.f, a1 = 0.f, a2 = 0.f;
    #pragma unroll 4
    for (int c = 0; c < 64; c++){
        float v = fmaxf(fmaf(d_sc0[c], d_h0[c*PTOT + p], d_bi0[c]), 0.f);
        a0 = fmaf(w1[c],       v, a0);
        a1 = fmaf(w1[64 + c],  v, a1);
        a2 = fmaf(w1[128 + c], v, a2);
    }
    d_h1[p] = a0; d_h1[PTOT + p] = a1; d_h1[2*PTOT + p] = a2;
}

// apply bn+relu -> new_xyz[p][3]
__global__ void ks3(){
    int p = blockIdx.x*blockDim.x + threadIdx.x;
    #pragma unroll
    for (int o = 0; o < 3; o++)
        d_nxyz[p*3 + o] = fmaxf(fmaf(d_sc1[o], d_h1[o*PTOT + p], d_bi1[o]), 0.f);
}

// transpose features: (B,C,N) -> (B,N,C)
__global__ void ktr(const float* __restrict__ feat){
    __shared__ float t[32][33];
    int b = blockIdx.z, n0 = blockIdx.x*32, c0 = blockIdx.y*32;
    for (int i = threadIdx.y; i < 32; i += 8)
        t[i][threadIdx.x] = feat[((size_t)b*CF + (c0+i))*NPT + n0 + threadIdx.x];
    __syncthreads();
    for (int i = threadIdx.y; i < 32; i += 8)
        d_featT[((size_t)b*NPT + (n0+i))*CF + c0 + threadIdx.x] = t[threadIdx.x][i];
}

// ball query: warp per query, first NS indices with d2 < R2, padded with first hit
__global__ void kballq(const float* __restrict__ bxyz){
    int gw = (blockIdx.x*blockDim.x + threadIdx.x) >> 5;
    int lane = threadIdx.x & 31;
    int b = gw >> 11;                 // / MQ
    float q0 = d_nxyz[gw*3+0], q1 = d_nxyz[gw*3+1], q2 = d_nxyz[gw*3+2];
    float qq = q0*q0 + q1*q1 + q2*q2;
    const float* xb = bxyz + (size_t)b*NPT*3;
    int cnt = 0, firstIdx = -1;
    for (int base = 0; base < NPT; base += 32){
        int n = base + lane;
        float x0 = xb[n*3+0], x1 = xb[n*3+1], x2 = xb[n*3+2];
        float xx = x0*x0 + x1*x1 + x2*x2;
        float dot = q0*x0 + q1*x1 + q2*x2;
        float d2 = (qq + xx) - 2.0f*dot;
        bool hit = d2 < R2;
        unsigned bal = __ballot_sync(0xffffffffu, hit);
        if (firstIdx < 0 && bal) firstIdx = base + __ffs(bal) - 1;
        if (hit){
            int pos = cnt + __popc(bal & ((1u << lane) - 1u));
            if (pos < NS) d_idx[gw*NS + pos] = n;
        }
        cnt += __popc(bal);
        if (cnt >= NS) break;
    }
    if (cnt < NS){
        int f = (firstIdx < 0) ? 0 : firstIdx;
        if (lane >= cnt) d_idx[gw*NS + lane] = f;
    }
}

// ---------------- GEMM 1: out0 = w0(128x131) @ [rel;feat], + channel stats ----------------
// smem: As [131][129] (k-major W), Bs [131][130] columns
#define G1_SMEM ((16900 + 131*130) * 4)
__global__ void __launch_bounds__(256, 1) kg1(const float* __restrict__ w0,
                                              const float* __restrict__ bxyz){
    extern __shared__ float sm[];
    float* As = sm;
    float* Bs = sm + 16900;
    const int tid = threadIdx.x;
    const int tx = tid & 15, ty = tid >> 4;
    const int jb = blockIdx.x * 128;

    for (int e = tid; e < 128*131; e += 256){
        int r = e / 131, k = e - r*131;
        As[k*129 + r] = w0[e];
    }
    {
        int col = tid >> 1, half = tid & 1;
        int j = jb + col;
        int b = j >> 16;
        int rem = j & 65535;
        int m = rem >> 5;
        int n = d_idx[j];
        const float* fp = d_featT + ((size_t)(b*NPT + n) * CF);
        int cb = half << 6;
        #pragma unroll
        for (int c4 = 0; c4 < 16; c4++){
            float4 v = *(const float4*)(fp + cb + c4*4);
            int kk = 3 + cb + c4*4;
            Bs[kk*130 + col]     = v.x;
            Bs[(kk+1)*130 + col] = v.y;
            Bs[(kk+2)*130 + col] = v.z;
            Bs[(kk+3)*130 + col] = v.w;
        }
        if (half == 0){
            const float* xp = bxyz + (size_t)(b*NPT + n)*3;
            const float* qp = d_nxyz + (size_t)(b*MQ + m)*3;
            Bs[col]       = xp[0] - qp[0];
            Bs[130 + col] = xp[1] - qp[1];
            Bs[260 + col] = xp[2] - qp[2];
        }
    }
    __syncthreads();

    unsigned long long acc[8][4];
    #pragma unroll
    for (int i = 0; i < 8; i++)
        #pragma unroll
        for (int j = 0; j < 4; j++) acc[i][j] = 0ull;

    for (int k = 0; k < 131; k++){
        unsigned long long av[8], bv[4];
        #pragma unroll
        for (int i = 0; i < 8; i++) av[i] = pack2(As[k*129 + ty + 16*i]);
        #pragma unroll
        for (int j = 0; j < 4; j++)
            bv[j] = *(const unsigned long long*)(Bs + k*130 + 2*tx + 32*j);
        #pragma unroll
        for (int i = 0; i < 8; i++)
            #pragma unroll
            for (int j = 0; j < 4; j++) acc[i][j] = ffma2(av[i], bv[j], acc[i][j]);
    }
    __syncthreads();

    float* red = sm;                 // 256 floats: [0:128) sum, [128:256) sq
    red[tid] = 0.f;
    __syncthreads();
    #pragma unroll
    for (int i = 0; i < 8; i++){
        int r = ty + 16*i;
        float rs = 0.f, rq = 0.f;
        #pragma unroll
        for (int j = 0; j < 4; j++){
            float lo, hi; unpack2(acc[i][j], lo, hi);
            int c = 2*tx + 32*j;
            *(float2*)(d_out0 + (size_t)r*COLS + jb + c) = make_float2(lo, hi);
            rs += lo + hi; rq += lo*lo + hi*hi;
        }
        atomicAdd(&red[r], rs);
        atomicAdd(&red[128 + r], rq);
    }
    __syncthreads();
    if (tid < 128){
        atomicAdd(&d_stats[tid],       red[tid]);
        atomicAdd(&d_stats[128 + tid], red[128 + tid]);
    }
}

// finalize BN scale/bias for mlp layers from accumulated stats
__global__ void kfm(int which, const float* __restrict__ g, const float* __restrict__ bb){
    int c = threadIdx.x;
    float inv = 1.0f / (float)COLS;
    int so = (which == 0) ? 0 : 256;
    int qo = (which == 0) ? 128 : 512;
    float mean = d_stats[so + c] * inv;
    float var  = d_stats[qo + c] * inv - mean*mean;
    float scl  = g[c] * rsqrtf(var + EPSV);
    if (which == 0){ d_scm0[c] = scl; d_bim0[c] = fmaf(-mean, scl, bb[c]); }
    else           { d_scm1[c] = scl; d_bim1[c] = fmaf(-mean, scl, bb[c]); }
}

// ---------------- GEMM 2: z1 = w1(256x128) @ relu(bn(out0)); fused stats + max/min pool ----------------
// grid (2048, 2): y = row half. smem: As [128][129], Bs [128][130]
#define G2_SMEM ((128*129 + 128*130) * 4)
__global__ void __launch_bounds__(256, 1) kg2(const float* __restrict__ w1){
    extern __shared__ float sm[];
    float* As = sm;
    float* Bs = sm + 128*129;
    const int tid = threadIdx.x;
    const int tx = tid & 15, ty = tid >> 4;
    const int jb = blockIdx.x * 128;
    const int rowOff = blockIdx.y * 128;

    for (int e = tid; e < 128*128; e += 256){
        int r = e >> 7, k = e & 127;
        As[k*129 + r] = w1[(rowOff + r)*128 + k];
    }
    for (int e = tid; e < 128*128; e += 256){
        int k = e >> 7, col = e & 127;
        float v = d_out0[(size_t)k*COLS + jb + col];
        Bs[k*130 + col] = fmaxf(fmaf(d_scm0[k], v, d_bim0[k]), 0.f);
    }
    __syncthreads();

    unsigned long long acc[8][4];
    #pragma unroll
    for (int i = 0; i < 8; i++)
        #pragma unroll
        for (int j = 0; j < 4; j++) acc[i][j] = 0ull;

    for (int k = 0; k < 128; k++){
        unsigned long long av[8], bv[4];
        #pragma unroll
        for (int i = 0; i < 8; i++) av[i] = pack2(As[k*129 + ty + 16*i]);
        #pragma unroll
        for (int j = 0; j < 4; j++)
            bv[j] = *(const unsigned long long*)(Bs + k*130 + 2*tx + 32*j);
        #pragma unroll
        for (int i = 0; i < 8; i++)
            #pragma unroll
            for (int j = 0; j < 4; j++) acc[i][j] = ffma2(av[i], bv[j], acc[i][j]);
    }
    __syncthreads();

    float* red = sm;                // 256 floats: [0:128) sum, [128:256) sq (local rows)
    red[tid] = 0.f;
    __syncthreads();
    #pragma unroll
    for (int i = 0; i < 8; i++){
        int rl = ty + 16*i;
        int rg = rowOff + rl;
        float rs = 0.f, rq = 0.f;
        #pragma unroll
        for (int j = 0; j < 4; j++){
            float lo, hi; unpack2(acc[i][j], lo, hi);
            rs += lo + hi; rq += lo*lo + hi*hi;
            float mx = fmaxf(lo, hi), mn = fminf(lo, hi);
            #pragma unroll
            for (int off = 8; off > 0; off >>= 1){
                mx = fmaxf(mx, __shfl_down_sync(0xffffffffu, mx, off, 16));
                mn = fminf(mn, __shfl_down_sync(0xffffffffu, mn, off, 16));
            }
            if (tx == 0){
                int q = (jb >> 5) + j;
                d_pmax[(size_t)rg*PTOT + q] = mx;
                d_pmin[(size_t)rg*PTOT + q] = mn;
            }
        }
        atomicAdd(&red[rl], rs);
        atomicAdd(&red[128 + rl], rq);
    }
    __syncthreads();
    if (tid < 128){
        atomicAdd(&d_stats[256 + rowOff + tid], red[tid]);
        atomicAdd(&d_stats[512 + rowOff + tid], red[128 + tid]);
    }
}

// final: out[p][c] = relu(s*pooled + t), pooled = max if s>=0 else min
__global__ void kfin(float* __restrict__ out){
    int c = threadIdx.x;
    int p = blockIdx.x;
    float s = d_scm1[c], t = d_bim1[c];
    float v = (s >= 0.f) ? d_pmax[(size_t)c*PTOT + p] : d_pmin[(size_t)c*PTOT + p];
    out[(size_t)p*256 + c] = fmaxf(fmaf(s, v, t), 0.f);
}

// ---------------- launch ----------------
extern "C" void kernel_launch(void* const* d_in, const int* in_sizes, int n_in,
                              void* d_out, int out_size){
    (void)in_sizes; (void)n_in; (void)out_size;
    const float* ffps = (const float*)d_in[0];
    const float* bxyz = (const float*)d_in[1];
    const float* bfeat= (const float*)d_in[2];
    const float* sw0  = (const float*)d_in[3];
    const float* sg0  = (const float*)d_in[4];
    const float* sb0  = (const float*)d_in[5];
    const float* sw1  = (const float*)d_in[6];
    const float* sg1  = (const float*)d_in[7];
    const float* sb1  = (const float*)d_in[8];
    const float* mw0  = (const float*)d_in[9];
    const float* mg0  = (const float*)d_in[10];
    const float* mb0  = (const float*)d_in[11];
    const float* mw1  = (const float*)d_in[12];
    const float* mg1  = (const float*)d_in[13];
    const float* mb1  = (const float*)d_in[14];
    float* out = (float*)d_out;

    cudaFuncSetAttribute(kg1, cudaFuncAttributeMaxDynamicSharedMemorySize, G1_SMEM);
    cudaFuncSetAttribute(kg2, cudaFuncAttributeMaxDynamicSharedMemorySize, G2_SMEM);

    kzero<<<3, 256>>>();
    ks1<<<PTOT/256, 256>>>(ffps, sw0);
    kstat<<<64, 256>>>(0, sg0, sb0);
    ks2<<<PTOT/256, 256>>>(sw1);
    kstat<<<3, 256>>>(1, sg1, sb1);
    ks3<<<PTOT/256, 256>>>();
    ktr<<<dim3(NPT/32, CF/32, BQ), dim3(32, 8)>>>(bfeat);
    kballq<<<PTOT/8, 256>>>(bxyz);
    kg1<<<COLS/128, 256, G1_SMEM>>>(mw0, bxyz);
    kfm<<<1, 128>>>(0, mg0, mb0);
    kg2<<<dim3(COLS/128, 2), 256, G2_SMEM>>>(mw1);
    kfm<<<1, 256>>>(1, mg1, mb1);
    kfin<<<PTOT, 256>>>(out);
}